// round 2
// baseline (speedup 1.0000x reference)
#include <cuda_runtime.h>
#include <math.h>

// ---------------- problem constants ----------------
#define BB   2
#define SS   2048
#define HID  768
#define NH   12
#define NKV  6
#define HD   64
#define MROWS (BB*SS)               // 4096
#define NQKV  (HID + 2*NKV*HD)      // 1536
#define NQEL  (HID*HID)             // 589824  (Wq, Wo)
#define NKEL  (NKV*HD*HID)          // 294912  (Wk, Wv)

// ---------------- device scratch (no allocations allowed) ----------------
__device__ float g_part[4*512];
__device__ float g_sums[4];
__device__ float g_qWqkv[NQKV*HID];     // rows: [Wq(768); Wk(384); Wv(384)] ternary
__device__ float g_qWo[HID*HID];
__device__ float g_qkv[MROWS*NQKV];     // raw qkv projection (pre-RoPE, pre-scale)
__device__ float g_q[BB*NH*SS*HD];
__device__ float g_k[BB*NKV*SS*HD];
__device__ float g_v[BB*NKV*SS*HD];
__device__ float g_ao[MROWS*HID];       // attention output [B,S,H]

// ---------------- weight |.| reduction (deterministic, two stage) ----------------
__global__ __launch_bounds__(256) void absum_kernel(const float* __restrict__ w, int n, int idx) {
    __shared__ float red[256];
    float s = 0.f;
    for (int i = blockIdx.x*256 + threadIdx.x; i < n; i += 512*256) s += fabsf(w[i]);
    red[threadIdx.x] = s;
    __syncthreads();
    #pragma unroll
    for (int k = 128; k > 0; k >>= 1) {
        if (threadIdx.x < k) red[threadIdx.x] += red[threadIdx.x + k];
        __syncthreads();
    }
    if (threadIdx.x == 0) g_part[idx*512 + blockIdx.x] = red[0];
}

__global__ __launch_bounds__(256) void finalize_kernel() {
    __shared__ float red[256];
    int idx = blockIdx.x;
    red[threadIdx.x] = g_part[idx*512 + threadIdx.x] + g_part[idx*512 + 256 + threadIdx.x];
    __syncthreads();
    #pragma unroll
    for (int k = 128; k > 0; k >>= 1) {
        if (threadIdx.x < k) red[threadIdx.x] += red[threadIdx.x + k];
        __syncthreads();
    }
    if (threadIdx.x == 0) g_sums[idx] = red[0];
}

// ---------------- ternary quantization ----------------
__global__ __launch_bounds__(256) void quant_kernel(const float* __restrict__ w,
                                                    float* __restrict__ qw,
                                                    int n, int idx, float invn) {
    int i = blockIdx.x*256 + threadIdx.x;
    if (i >= n) return;
    float thr = 0.7f * g_sums[idx] * invn;
    float x = w[i];
    qw[i] = (fabsf(x) >= thr) ? (x > 0.f ? 1.f : -1.f) : 0.f;
}

// ---------------- generic C = A * B^T GEMM (fp32 SIMT, 128x128x16 tile) ----------------
// A: [M,K] row-major, Bm: [N,K] row-major, C: [M,N]. Optional scale = g_sums[scale_idx]*invn.
__global__ __launch_bounds__(256) void gemm_nt(const float* __restrict__ A,
                                               const float* __restrict__ Bm,
                                               float* __restrict__ C,
                                               int M, int N, int K,
                                               int scale_idx, float invn) {
    __shared__ float As[16][132];
    __shared__ float Bs[16][132];
    int tid = threadIdx.x;
    int tx = tid & 15, ty = tid >> 4;
    int bm = blockIdx.y * 128, bn = blockIdx.x * 128;

    float acc[8][8];
    #pragma unroll
    for (int i = 0; i < 8; i++)
        #pragma unroll
        for (int j = 0; j < 8; j++) acc[i][j] = 0.f;

    for (int k0 = 0; k0 < K; k0 += 16) {
        #pragma unroll
        for (int i = 0; i < 2; i++) {
            int f = tid + i*256;            // 0..511 float4 slots
            int row = f >> 2;
            int kc = (f & 3) << 2;
            float4 va = *(const float4*)(A + (size_t)(bm + row)*K + k0 + kc);
            As[kc+0][row] = va.x; As[kc+1][row] = va.y;
            As[kc+2][row] = va.z; As[kc+3][row] = va.w;
            float4 vb = *(const float4*)(Bm + (size_t)(bn + row)*K + k0 + kc);
            Bs[kc+0][row] = vb.x; Bs[kc+1][row] = vb.y;
            Bs[kc+2][row] = vb.z; Bs[kc+3][row] = vb.w;
        }
        __syncthreads();
        #pragma unroll
        for (int kk = 0; kk < 16; kk++) {
            float a[8];
            float4 a0 = *(const float4*)&As[kk][ty*8];
            float4 a1 = *(const float4*)&As[kk][ty*8 + 4];
            a[0]=a0.x; a[1]=a0.y; a[2]=a0.z; a[3]=a0.w;
            a[4]=a1.x; a[5]=a1.y; a[6]=a1.z; a[7]=a1.w;
            #pragma unroll
            for (int j = 0; j < 8; j++) {
                float bv = Bs[kk][tx + 16*j];
                #pragma unroll
                for (int i = 0; i < 8; i++) acc[i][j] += a[i]*bv;
            }
        }
        __syncthreads();
    }
    float scale = (scale_idx >= 0) ? g_sums[scale_idx]*invn : 1.f;
    #pragma unroll
    for (int i = 0; i < 8; i++)
        #pragma unroll
        for (int j = 0; j < 8; j++)
            C[(size_t)(bm + ty*8 + i)*N + bn + tx + 16*j] = acc[i][j]*scale;
}

// ---------------- RoPE + scale + scatter to per-head layout ----------------
__global__ __launch_bounds__(256) void rope_scatter() {
    int e = blockIdx.x*256 + threadIdx.x;        // over MROWS*NQKV
    int m = e / NQKV, n = e - m*NQKV;
    int b = m >> 11, s = m & (SS-1);
    float val = g_qkv[e];

    if (n < HID) {                                // Q
        float scale = g_sums[0] * (1.f/(float)NQEL);
        int h = n >> 6, d = n & 63;
        int fi = d & 31;
        float invf = (float)exp(-9.210340371976184 * ((double)fi / 32.0));
        float ang = (float)s * invf;
        float c = cosf(ang), sn = sinf(ang);
        int partner = (d < 32) ? (e + 32) : (e - 32);
        float pv = g_qkv[partner] * scale;
        float vq = val * scale;
        float out = (d < 32) ? (vq*c - pv*sn) : (vq*c + pv*sn);
        g_q[((size_t)(b*NH + h)*SS + s)*HD + d] = out;
    } else if (n < HID + NKV*HD) {                // K
        float scale = g_sums[1] * (1.f/(float)NKEL);
        int nn = n - HID;
        int h = nn >> 6, d = nn & 63;
        int fi = d & 31;
        float invf = (float)exp(-9.210340371976184 * ((double)fi / 32.0));
        float ang = (float)s * invf;
        float c = cosf(ang), sn = sinf(ang);
        int partner = (d < 32) ? (e + 32) : (e - 32);
        float pv = g_qkv[partner] * scale;
        float vk = val * scale;
        float out = (d < 32) ? (vk*c - pv*sn) : (vk*c + pv*sn);
        g_k[((size_t)(b*NKV + h)*SS + s)*HD + d] = out;
    } else {                                      // V (no RoPE)
        float scale = g_sums[2] * (1.f/(float)NKEL);
        int nn = n - HID - NKV*HD;
        int h = nn >> 6, d = nn & 63;
        g_v[((size_t)(b*NKV + h)*SS + s)*HD + d] = val * scale;
    }
}

// ---------------- flash attention (fp32, 64-query tile, full attention, GQA) ----------------
#define SMSTRIDE 68
__global__ __launch_bounds__(256) void attn_kernel() {
    extern __shared__ float sm[];
    float* Qs = sm;
    float* Ks = sm + 64*SMSTRIDE;
    float* Vs = sm + 2*64*SMSTRIDE;
    float* Ps = sm + 3*64*SMSTRIDE;

    int b = blockIdx.z, h = blockIdx.y;
    int s0 = blockIdx.x * 64;
    int hk = h >> 1;                      // groups = 2
    int tid = threadIdx.x;
    int tx = tid & 15, ty = tid >> 4;

    const float* qptr  = g_q + ((size_t)(b*NH  + h )*SS + s0)*HD;
    const float* kbase = g_k +  (size_t)(b*NKV + hk)*SS*HD;
    const float* vbase = g_v +  (size_t)(b*NKV + hk)*SS*HD;

    // load Q tile [64,64]
    #pragma unroll
    for (int i = 0; i < 4; i++) {
        int f = tid + i*256;              // 0..1023 float4
        int row = f >> 4, d4 = (f & 15) << 2;
        *(float4*)(Qs + row*SMSTRIDE + d4) = *(const float4*)(qptr + row*HD + d4);
    }

    float m_run[4], l_run[4], o[4][4];
    #pragma unroll
    for (int i = 0; i < 4; i++) {
        m_run[i] = -1e30f; l_run[i] = 0.f;
        #pragma unroll
        for (int j = 0; j < 4; j++) o[i][j] = 0.f;
    }

    for (int t0 = 0; t0 < SS; t0 += 64) {
        __syncthreads();   // Q ready (iter 0) / prev PV done before KV overwrite
        #pragma unroll
        for (int i = 0; i < 4; i++) {
            int f = tid + i*256;
            int row = f >> 4, d4 = (f & 15) << 2;
            *(float4*)(Ks + row*SMSTRIDE + d4) = *(const float4*)(kbase + (size_t)(t0+row)*HD + d4);
            *(float4*)(Vs + row*SMSTRIDE + d4) = *(const float4*)(vbase + (size_t)(t0+row)*HD + d4);
        }
        __syncthreads();

        // S = Q K^T for rows (ty+16i), cols (tx+16j)
        float sacc[4][4];
        #pragma unroll
        for (int i = 0; i < 4; i++)
            #pragma unroll
            for (int j = 0; j < 4; j++) sacc[i][j] = 0.f;

        for (int d = 0; d < 64; d += 4) {
            float4 q4[4], k4[4];
            #pragma unroll
            for (int i = 0; i < 4; i++) q4[i] = *(const float4*)(Qs + (ty + 16*i)*SMSTRIDE + d);
            #pragma unroll
            for (int j = 0; j < 4; j++) k4[j] = *(const float4*)(Ks + (tx + 16*j)*SMSTRIDE + d);
            #pragma unroll
            for (int i = 0; i < 4; i++)
                #pragma unroll
                for (int j = 0; j < 4; j++) {
                    sacc[i][j] += q4[i].x*k4[j].x;
                    sacc[i][j] += q4[i].y*k4[j].y;
                    sacc[i][j] += q4[i].z*k4[j].z;
                    sacc[i][j] += q4[i].w*k4[j].w;
                }
        }

        // online softmax (rows shared by the 16 tx-lanes of each ty group)
        #pragma unroll
        for (int i = 0; i < 4; i++) {
            #pragma unroll
            for (int j = 0; j < 4; j++) sacc[i][j] *= 0.125f;  // 1/sqrt(64)
            float mloc = fmaxf(fmaxf(sacc[i][0], sacc[i][1]), fmaxf(sacc[i][2], sacc[i][3]));
            #pragma unroll
            for (int mm = 8; mm > 0; mm >>= 1)
                mloc = fmaxf(mloc, __shfl_xor_sync(0xffffffffu, mloc, mm));
            float mnew = fmaxf(m_run[i], mloc);
            float alpha = __expf(m_run[i] - mnew);
            float ls = 0.f;
            #pragma unroll
            for (int j = 0; j < 4; j++) {
                float p = __expf(sacc[i][j] - mnew);
                Ps[(ty + 16*i)*SMSTRIDE + tx + 16*j] = p;
                ls += p;
            }
            #pragma unroll
            for (int mm = 8; mm > 0; mm >>= 1)
                ls += __shfl_xor_sync(0xffffffffu, ls, mm);
            l_run[i] = l_run[i]*alpha + ls;
            #pragma unroll
            for (int j = 0; j < 4; j++) o[i][j] *= alpha;
            m_run[i] = mnew;
        }
        __syncthreads();   // Ps visible

        // O += P @ V  (o cols d = tx*4 + j)
        #pragma unroll 4
        for (int c = 0; c < 64; c++) {
            float4 v4 = *(const float4*)(Vs + c*SMSTRIDE + tx*4);
            #pragma unroll
            for (int i = 0; i < 4; i++) {
                float p = Ps[(ty + 16*i)*SMSTRIDE + c];
                o[i][0] += p*v4.x; o[i][1] += p*v4.y;
                o[i][2] += p*v4.z; o[i][3] += p*v4.w;
            }
        }
    }

    // epilogue: divide by l, write [B,S,H] layout
    float* outp = g_ao + ((size_t)b*SS + s0)*HID + h*HD;
    #pragma unroll
    for (int i = 0; i < 4; i++) {
        float inv = 1.f / l_run[i];
        float4 r;
        r.x = o[i][0]*inv; r.y = o[i][1]*inv; r.z = o[i][2]*inv; r.w = o[i][3]*inv;
        *(float4*)(outp + (size_t)(ty + 16*i)*HID + tx*4) = r;
    }
}

// ---------------- launch ----------------
extern "C" void kernel_launch(void* const* d_in, const int* in_sizes, int n_in,
                              void* d_out, int out_size) {
    const float* hs = (const float*)d_in[0];
    const float* Wq = (const float*)d_in[1];
    const float* Wk = (const float*)d_in[2];
    const float* Wv = (const float*)d_in[3];
    const float* Wo = (const float*)d_in[4];
    float* out = (float*)d_out;

    float *p_qWqkv, *p_qWo, *p_qkv, *p_ao;
    cudaGetSymbolAddress((void**)&p_qWqkv, g_qWqkv);
    cudaGetSymbolAddress((void**)&p_qWo,  g_qWo);
    cudaGetSymbolAddress((void**)&p_qkv,  g_qkv);
    cudaGetSymbolAddress((void**)&p_ao,   g_ao);

    cudaFuncSetAttribute(attn_kernel, cudaFuncAttributeMaxDynamicSharedMemorySize,
                         4*64*SMSTRIDE*(int)sizeof(float));

    // 1) weight scales (deterministic)
    absum_kernel<<<512, 256>>>(Wq, NQEL, 0);
    absum_kernel<<<512, 256>>>(Wk, NKEL, 1);
    absum_kernel<<<512, 256>>>(Wv, NKEL, 2);
    absum_kernel<<<512, 256>>>(Wo, NQEL, 3);
    finalize_kernel<<<4, 256>>>();

    // 2) ternary quantize into stacked QKV weight + Wo
    quant_kernel<<<NQEL/256, 256>>>(Wq, p_qWqkv,                 NQEL, 0, 1.f/(float)NQEL);
    quant_kernel<<<NKEL/256, 256>>>(Wk, p_qWqkv + HID*HID,       NKEL, 1, 1.f/(float)NKEL);
    quant_kernel<<<NKEL/256, 256>>>(Wv, p_qWqkv + (HID+NKV*HD)*HID, NKEL, 2, 1.f/(float)NKEL);
    quant_kernel<<<NQEL/256, 256>>>(Wo, p_qWo,                   NQEL, 3, 1.f/(float)NQEL);

    // 3) QKV projection: [4096,768] x [1536,768]^T -> [4096,1536]
    gemm_nt<<<dim3(NQKV/128, MROWS/128), 256>>>(hs, p_qWqkv, p_qkv,
                                                MROWS, NQKV, HID, -1, 1.f);

    // 4) scale + RoPE + scatter to head layouts
    rope_scatter<<<(MROWS*NQKV)/256, 256>>>();

    // 5) flash attention
    attn_kernel<<<dim3(SS/64, NH, BB), 256, 4*64*SMSTRIDE*(int)sizeof(float)>>>();

    // 6) output projection with Wo scale -> d_out
    gemm_nt<<<dim3(HID/128, MROWS/128), 256>>>(p_ao, p_qWo, out,
                                               MROWS, HID, HID, 3, 1.f/(float)NQEL);
}

// round 3
// speedup vs baseline: 2.1793x; 2.1793x over previous
#include <cuda_runtime.h>
#include <math.h>

// ---------------- problem constants ----------------
#define BB   2
#define SS   2048
#define HID  768
#define NH   12
#define NKV  6
#define HD   64
#define MROWS (BB*SS)               // 4096
#define NQKV  (HID + 2*NKV*HD)      // 1536
#define NQEL  (HID*HID)             // 589824  (Wq, Wo)
#define NKEL  (NKV*HD*HID)          // 294912  (Wk, Wv)

// ---------------- device scratch (no allocations allowed) ----------------
__device__ float g_part[4*512];
__device__ float g_sums[4];
__device__ float g_qWqkv[NQKV*HID];     // rows: [Wq(768); Wk(384); Wv(384)] ternary
__device__ float g_qWo[HID*HID];
__device__ float g_qkv[MROWS*NQKV];     // raw qkv projection (pre-RoPE, pre-scale)
__device__ float g_q[BB*NH*SS*HD];
__device__ float g_k[BB*NKV*SS*HD];
__device__ float g_v[BB*NKV*SS*HD];
__device__ float g_ao[MROWS*HID];       // attention output [B,S,H]

// ---------------- tf32 helpers ----------------
__device__ __forceinline__ unsigned f2tf32(float f) {
    unsigned r;
    asm("cvt.rna.tf32.f32 %0, %1;" : "=r"(r) : "f"(f));
    return r;
}

__device__ __forceinline__ void mma_tf32(float c[4],
                                         unsigned a0, unsigned a1, unsigned a2, unsigned a3,
                                         unsigned b0, unsigned b1) {
    asm volatile(
        "mma.sync.aligned.m16n8k8.row.col.f32.tf32.tf32.f32 "
        "{%0,%1,%2,%3}, {%4,%5,%6,%7}, {%8,%9}, {%0,%1,%2,%3};\n"
        : "+f"(c[0]), "+f"(c[1]), "+f"(c[2]), "+f"(c[3])
        : "r"(a0), "r"(a1), "r"(a2), "r"(a3), "r"(b0), "r"(b1));
}

// ---------------- weight |.| reduction (deterministic, two stage) ----------------
__global__ __launch_bounds__(256) void absum_kernel(const float* __restrict__ w, int n, int idx) {
    __shared__ float red[256];
    float s = 0.f;
    for (int i = blockIdx.x*256 + threadIdx.x; i < n; i += 512*256) s += fabsf(w[i]);
    red[threadIdx.x] = s;
    __syncthreads();
    #pragma unroll
    for (int k = 128; k > 0; k >>= 1) {
        if (threadIdx.x < k) red[threadIdx.x] += red[threadIdx.x + k];
        __syncthreads();
    }
    if (threadIdx.x == 0) g_part[idx*512 + blockIdx.x] = red[0];
}

__global__ __launch_bounds__(256) void finalize_kernel() {
    __shared__ float red[256];
    int idx = blockIdx.x;
    red[threadIdx.x] = g_part[idx*512 + threadIdx.x] + g_part[idx*512 + 256 + threadIdx.x];
    __syncthreads();
    #pragma unroll
    for (int k = 128; k > 0; k >>= 1) {
        if (threadIdx.x < k) red[threadIdx.x] += red[threadIdx.x + k];
        __syncthreads();
    }
    if (threadIdx.x == 0) g_sums[idx] = red[0];
}

// ---------------- ternary quantization ----------------
__global__ __launch_bounds__(256) void quant_kernel(const float* __restrict__ w,
                                                    float* __restrict__ qw,
                                                    int n, int idx, float invn) {
    int i = blockIdx.x*256 + threadIdx.x;
    if (i >= n) return;
    float thr = 0.7f * g_sums[idx] * invn;
    float x = w[i];
    qw[i] = (fabsf(x) >= thr) ? (x > 0.f ? 1.f : -1.f) : 0.f;
}

// ---------------- tf32 tensor-core GEMM: C = A * B^T ----------------
// A: [M,K] row-major fp32, Bm: [N,K] row-major fp32, C: [M,N].
// Block tile 128x128, k-tile 32, 8 warps as 2(m) x 4(n), warp tile 64x32.
#define GSTR 36
__global__ __launch_bounds__(256) void gemm_tf32(const float* __restrict__ A,
                                                 const float* __restrict__ Bm,
                                                 float* __restrict__ C,
                                                 int M, int N, int K,
                                                 int scale_idx, float invn) {
    __shared__ unsigned As[128*GSTR];
    __shared__ unsigned Bs[128*GSTR];
    int tid = threadIdx.x;
    int wid = tid >> 5, lane = tid & 31;
    int wm = wid & 1, wn = wid >> 1;          // 2 x 4 warp grid
    int g = lane >> 2, tg = lane & 3;
    int bm = blockIdx.y * 128, bn = blockIdx.x * 128;

    int lr = tid >> 3;                        // 0..31 loader row
    int lc = (tid & 7) * 4;                   // loader col (float4)

    float acc[4][4][4];
    #pragma unroll
    for (int mt = 0; mt < 4; mt++)
        #pragma unroll
        for (int nt = 0; nt < 4; nt++)
            #pragma unroll
            for (int r = 0; r < 4; r++) acc[mt][nt][r] = 0.f;

    for (int k0 = 0; k0 < K; k0 += 32) {
        #pragma unroll
        for (int i = 0; i < 4; i++) {
            int row = lr + 32*i;
            float4 va = *(const float4*)(A + (size_t)(bm + row)*K + k0 + lc);
            uint4 ua; ua.x = f2tf32(va.x); ua.y = f2tf32(va.y); ua.z = f2tf32(va.z); ua.w = f2tf32(va.w);
            *(uint4*)&As[row*GSTR + lc] = ua;
            float4 vb = *(const float4*)(Bm + (size_t)(bn + row)*K + k0 + lc);
            uint4 ub; ub.x = f2tf32(vb.x); ub.y = f2tf32(vb.y); ub.z = f2tf32(vb.z); ub.w = f2tf32(vb.w);
            *(uint4*)&Bs[row*GSTR + lc] = ub;
        }
        __syncthreads();
        #pragma unroll
        for (int kk = 0; kk < 32; kk += 8) {
            unsigned af[4][4], bf[4][2];
            #pragma unroll
            for (int mt = 0; mt < 4; mt++) {
                int row = wm*64 + mt*16;
                af[mt][0] = As[(row + g    )*GSTR + kk + tg    ];
                af[mt][1] = As[(row + 8 + g)*GSTR + kk + tg    ];
                af[mt][2] = As[(row + g    )*GSTR + kk + tg + 4];
                af[mt][3] = As[(row + 8 + g)*GSTR + kk + tg + 4];
            }
            #pragma unroll
            for (int nt = 0; nt < 4; nt++) {
                int col = wn*32 + nt*8;
                bf[nt][0] = Bs[(col + g)*GSTR + kk + tg    ];
                bf[nt][1] = Bs[(col + g)*GSTR + kk + tg + 4];
            }
            #pragma unroll
            for (int mt = 0; mt < 4; mt++)
                #pragma unroll
                for (int nt = 0; nt < 4; nt++)
                    mma_tf32(acc[mt][nt], af[mt][0], af[mt][1], af[mt][2], af[mt][3],
                             bf[nt][0], bf[nt][1]);
        }
        __syncthreads();
    }

    float scale = (scale_idx >= 0) ? g_sums[scale_idx]*invn : 1.f;
    #pragma unroll
    for (int mt = 0; mt < 4; mt++) {
        int row = bm + wm*64 + mt*16 + g;
        #pragma unroll
        for (int nt = 0; nt < 4; nt++) {
            int col = bn + wn*32 + nt*8 + 2*tg;
            float2 v0; v0.x = acc[mt][nt][0]*scale; v0.y = acc[mt][nt][1]*scale;
            *(float2*)(C + (size_t)row*N + col) = v0;
            float2 v1; v1.x = acc[mt][nt][2]*scale; v1.y = acc[mt][nt][3]*scale;
            *(float2*)(C + (size_t)(row + 8)*N + col) = v1;
        }
    }
}

// ---------------- RoPE + scale + scatter to per-head layout ----------------
__global__ __launch_bounds__(256) void rope_scatter() {
    int e = blockIdx.x*256 + threadIdx.x;        // over MROWS*NQKV
    int m = e / NQKV, n = e - m*NQKV;
    int b = m >> 11, s = m & (SS-1);
    float val = g_qkv[e];

    if (n < HID) {                                // Q
        float scale = g_sums[0] * (1.f/(float)NQEL);
        int h = n >> 6, d = n & 63;
        int fi = d & 31;
        float invf = (float)exp(-9.210340371976184 * ((double)fi / 32.0));
        float ang = (float)s * invf;
        float c = cosf(ang), sn = sinf(ang);
        int partner = (d < 32) ? (e + 32) : (e - 32);
        float pv = g_qkv[partner] * scale;
        float vq = val * scale;
        float out = (d < 32) ? (vq*c - pv*sn) : (vq*c + pv*sn);
        g_q[((size_t)(b*NH + h)*SS + s)*HD + d] = out;
    } else if (n < HID + NKV*HD) {                // K
        float scale = g_sums[1] * (1.f/(float)NKEL);
        int nn = n - HID;
        int h = nn >> 6, d = nn & 63;
        int fi = d & 31;
        float invf = (float)exp(-9.210340371976184 * ((double)fi / 32.0));
        float ang = (float)s * invf;
        float c = cosf(ang), sn = sinf(ang);
        int partner = (d < 32) ? (e + 32) : (e - 32);
        float pv = g_qkv[partner] * scale;
        float vk = val * scale;
        float out = (d < 32) ? (vk*c - pv*sn) : (vk*c + pv*sn);
        g_k[((size_t)(b*NKV + h)*SS + s)*HD + d] = out;
    } else {                                      // V (no RoPE)
        float scale = g_sums[2] * (1.f/(float)NKEL);
        int nn = n - HID - NKV*HD;
        int h = nn >> 6, d = nn & 63;
        g_v[((size_t)(b*NKV + h)*SS + s)*HD + d] = val * scale;
    }
}

// ---------------- flash attention, tf32 mma ----------------
// Block: 256 threads (8 warps). Q tile 128 rows (warp w owns rows w*16..w*16+15).
// KV tile 64. Q fragments register-resident; P round-trips through smem (tf32).
#define KSTR 68
#define VSTR 72
#define PSTR 68
#define ATT_SMEM ((64*KSTR + 64*VSTR + 128*PSTR)*4)

__global__ __launch_bounds__(256) void attn_kernel() {
    extern __shared__ unsigned smu[];
    unsigned* Ks = smu;                 // [s(64)][d] stride 68
    unsigned* Vs = Ks + 64*KSTR;        // [s(64)][d] stride 72
    unsigned* Ps = Vs + 64*VSTR;        // [m(128)][s(64)] stride 68 (also Q staging)

    int b = blockIdx.z, h = blockIdx.y;
    int s0 = blockIdx.x * 128;
    int hk = h >> 1;                    // GQA groups = 2
    int tid = threadIdx.x;
    int wid = tid >> 5, lane = tid & 31;
    int g = lane >> 2, tg = lane & 3;
    int wr = wid * 16;                  // warp's row offset within Q tile

    const float* qptr  = g_q + ((size_t)(b*NH  + h )*SS + s0)*HD;
    const float* kbase = g_k +  (size_t)(b*NKV + hk)*SS*HD;
    const float* vbase = g_v +  (size_t)(b*NKV + hk)*SS*HD;

    // stage Q tile [128][64] into Ps (tf32), then pull fragments into registers
    #pragma unroll
    for (int i = 0; i < 8; i++) {
        int row = (tid >> 4) + i*16;
        int col = (tid & 15) * 4;
        float4 q = *(const float4*)(qptr + (size_t)row*HD + col);
        uint4 u; u.x = f2tf32(q.x); u.y = f2tf32(q.y); u.z = f2tf32(q.z); u.w = f2tf32(q.w);
        *(uint4*)&Ps[row*PSTR + col] = u;
    }
    __syncthreads();
    unsigned qf[8][4];
    #pragma unroll
    for (int kt = 0; kt < 8; kt++) {
        qf[kt][0] = Ps[(wr + g    )*PSTR + kt*8 + tg    ];
        qf[kt][1] = Ps[(wr + 8 + g)*PSTR + kt*8 + tg    ];
        qf[kt][2] = Ps[(wr + g    )*PSTR + kt*8 + tg + 4];
        qf[kt][3] = Ps[(wr + 8 + g)*PSTR + kt*8 + tg + 4];
    }

    float o[8][4];
    #pragma unroll
    for (int nt = 0; nt < 8; nt++)
        #pragma unroll
        for (int r = 0; r < 4; r++) o[nt][r] = 0.f;
    float m0 = -1e30f, m1 = -1e30f, l0 = 0.f, l1 = 0.f;

    for (int t0 = 0; t0 < SS; t0 += 64) {
        __syncthreads();   // protects Ks/Vs (prev iter readers) and Ps/qf ordering (iter 0)
        #pragma unroll
        for (int i = 0; i < 4; i++) {
            int row = (tid >> 4) + i*16;     // 0..63
            int col = (tid & 15) * 4;
            float4 kv = *(const float4*)(kbase + (size_t)(t0 + row)*HD + col);
            uint4 uk; uk.x = f2tf32(kv.x); uk.y = f2tf32(kv.y); uk.z = f2tf32(kv.z); uk.w = f2tf32(kv.w);
            *(uint4*)&Ks[row*KSTR + col] = uk;
            float4 vv = *(const float4*)(vbase + (size_t)(t0 + row)*HD + col);
            uint4 uv; uv.x = f2tf32(vv.x); uv.y = f2tf32(vv.y); uv.z = f2tf32(vv.z); uv.w = f2tf32(vv.w);
            *(uint4*)&Vs[row*VSTR + col] = uv;
        }
        __syncthreads();

        // S = Q K^T  (warp: 16 x 64)
        float sacc[8][4];
        #pragma unroll
        for (int nt = 0; nt < 8; nt++)
            #pragma unroll
            for (int r = 0; r < 4; r++) sacc[nt][r] = 0.f;

        #pragma unroll
        for (int kt = 0; kt < 8; kt++) {
            #pragma unroll
            for (int nt = 0; nt < 8; nt++) {
                unsigned b0 = Ks[(nt*8 + g)*KSTR + kt*8 + tg    ];
                unsigned b1 = Ks[(nt*8 + g)*KSTR + kt*8 + tg + 4];
                mma_tf32(sacc[nt], qf[kt][0], qf[kt][1], qf[kt][2], qf[kt][3], b0, b1);
            }
        }

        // online softmax. Thread's rows: r0 = wr+g (c0,c1), r1 = wr+8+g (c2,c3).
        float mx0 = -1e30f, mx1 = -1e30f;
        #pragma unroll
        for (int nt = 0; nt < 8; nt++) {
            sacc[nt][0] *= 0.125f; sacc[nt][1] *= 0.125f;
            sacc[nt][2] *= 0.125f; sacc[nt][3] *= 0.125f;
            mx0 = fmaxf(mx0, fmaxf(sacc[nt][0], sacc[nt][1]));
            mx1 = fmaxf(mx1, fmaxf(sacc[nt][2], sacc[nt][3]));
        }
        mx0 = fmaxf(mx0, __shfl_xor_sync(0xffffffffu, mx0, 1));
        mx0 = fmaxf(mx0, __shfl_xor_sync(0xffffffffu, mx0, 2));
        mx1 = fmaxf(mx1, __shfl_xor_sync(0xffffffffu, mx1, 1));
        mx1 = fmaxf(mx1, __shfl_xor_sync(0xffffffffu, mx1, 2));
        float mn0 = fmaxf(m0, mx0), mn1 = fmaxf(m1, mx1);
        float al0 = __expf(m0 - mn0), al1 = __expf(m1 - mn1);
        float ls0 = 0.f, ls1 = 0.f;
        #pragma unroll
        for (int nt = 0; nt < 8; nt++) {
            float p0 = __expf(sacc[nt][0] - mn0);
            float p1 = __expf(sacc[nt][1] - mn0);
            float p2 = __expf(sacc[nt][2] - mn1);
            float p3 = __expf(sacc[nt][3] - mn1);
            ls0 += p0 + p1; ls1 += p2 + p3;
            uint2 u0; u0.x = f2tf32(p0); u0.y = f2tf32(p1);
            *(uint2*)&Ps[(wr + g    )*PSTR + nt*8 + 2*tg] = u0;
            uint2 u1; u1.x = f2tf32(p2); u1.y = f2tf32(p3);
            *(uint2*)&Ps[(wr + 8 + g)*PSTR + nt*8 + 2*tg] = u1;
        }
        ls0 += __shfl_xor_sync(0xffffffffu, ls0, 1);
        ls0 += __shfl_xor_sync(0xffffffffu, ls0, 2);
        ls1 += __shfl_xor_sync(0xffffffffu, ls1, 1);
        ls1 += __shfl_xor_sync(0xffffffffu, ls1, 2);
        l0 = l0*al0 + ls0; l1 = l1*al1 + ls1;
        m0 = mn0; m1 = mn1;
        #pragma unroll
        for (int nt = 0; nt < 8; nt++) {
            o[nt][0] *= al0; o[nt][1] *= al0;
            o[nt][2] *= al1; o[nt][3] *= al1;
        }
        __syncwarp();      // P tiles are per-warp private: warp-level sync suffices

        // O += P @ V   (warp: 16 x 64, K = 64)
        #pragma unroll
        for (int kt = 0; kt < 8; kt++) {
            unsigned a0 = Ps[(wr + g    )*PSTR + kt*8 + tg    ];
            unsigned a1 = Ps[(wr + 8 + g)*PSTR + kt*8 + tg    ];
            unsigned a2 = Ps[(wr + g    )*PSTR + kt*8 + tg + 4];
            unsigned a3 = Ps[(wr + 8 + g)*PSTR + kt*8 + tg + 4];
            #pragma unroll
            for (int nt = 0; nt < 8; nt++) {
                unsigned b0 = Vs[(kt*8 + tg    )*VSTR + nt*8 + g];
                unsigned b1 = Vs[(kt*8 + tg + 4)*VSTR + nt*8 + g];
                mma_tf32(o[nt], a0, a1, a2, a3, b0, b1);
            }
        }
    }

    // epilogue: divide by l, write [B,S,H]
    float inv0 = 1.f / l0, inv1 = 1.f / l1;
    float* op = g_ao + ((size_t)b*SS + s0 + wr)*HID + h*HD;
    #pragma unroll
    for (int nt = 0; nt < 8; nt++) {
        int col = nt*8 + 2*tg;
        float2 v0; v0.x = o[nt][0]*inv0; v0.y = o[nt][1]*inv0;
        *(float2*)(op + (size_t)(g    )*HID + col) = v0;
        float2 v1; v1.x = o[nt][2]*inv1; v1.y = o[nt][3]*inv1;
        *(float2*)(op + (size_t)(8 + g)*HID + col) = v1;
    }
}

// ---------------- launch ----------------
extern "C" void kernel_launch(void* const* d_in, const int* in_sizes, int n_in,
                              void* d_out, int out_size) {
    const float* hs = (const float*)d_in[0];
    const float* Wq = (const float*)d_in[1];
    const float* Wk = (const float*)d_in[2];
    const float* Wv = (const float*)d_in[3];
    const float* Wo = (const float*)d_in[4];
    float* out = (float*)d_out;

    float *p_qWqkv, *p_qWo, *p_qkv, *p_ao;
    cudaGetSymbolAddress((void**)&p_qWqkv, g_qWqkv);
    cudaGetSymbolAddress((void**)&p_qWo,  g_qWo);
    cudaGetSymbolAddress((void**)&p_qkv,  g_qkv);
    cudaGetSymbolAddress((void**)&p_ao,   g_ao);

    cudaFuncSetAttribute(attn_kernel, cudaFuncAttributeMaxDynamicSharedMemorySize, ATT_SMEM);

    // 1) weight scales (deterministic)
    absum_kernel<<<512, 256>>>(Wq, NQEL, 0);
    absum_kernel<<<512, 256>>>(Wk, NKEL, 1);
    absum_kernel<<<512, 256>>>(Wv, NKEL, 2);
    absum_kernel<<<512, 256>>>(Wo, NQEL, 3);
    finalize_kernel<<<4, 256>>>();

    // 2) ternary quantize into stacked QKV weight + Wo
    quant_kernel<<<NQEL/256, 256>>>(Wq, p_qWqkv,                    NQEL, 0, 1.f/(float)NQEL);
    quant_kernel<<<NKEL/256, 256>>>(Wk, p_qWqkv + HID*HID,          NKEL, 1, 1.f/(float)NKEL);
    quant_kernel<<<NKEL/256, 256>>>(Wv, p_qWqkv + (HID+NKV*HD)*HID, NKEL, 2, 1.f/(float)NKEL);
    quant_kernel<<<NQEL/256, 256>>>(Wo, p_qWo,                      NQEL, 3, 1.f/(float)NQEL);

    // 3) QKV projection (tf32 tensor cores): [4096,768] x [1536,768]^T
    gemm_tf32<<<dim3(NQKV/128, MROWS/128), 256>>>(hs, p_qWqkv, p_qkv,
                                                  MROWS, NQKV, HID, -1, 1.f);

    // 4) scale + RoPE + scatter to head layouts
    rope_scatter<<<(MROWS*NQKV)/256, 256>>>();

    // 5) flash attention (tf32 tensor cores)
    attn_kernel<<<dim3(SS/128, NH, BB), 256, ATT_SMEM>>>();

    // 6) output projection with Wo scale -> d_out
    gemm_tf32<<<dim3(HID/128, MROWS/128), 256>>>(p_ao, p_qWo, out,
                                                 MROWS, HID, HID, 3, 1.f/(float)NQEL);
}

// round 4
// speedup vs baseline: 4.6388x; 2.1286x over previous
#include <cuda_runtime.h>
#include <cuda_fp16.h>
#include <math.h>

// ---------------- problem constants ----------------
#define BB   2
#define SS   2048
#define HID  768
#define NH   12
#define NKV  6
#define HD   64
#define MROWS (BB*SS)               // 4096
#define NQKV  (HID + 2*NKV*HD)      // 1536
#define NQEL  (HID*HID)             // 589824  (Wq, Wo)
#define NKEL  (NKV*HD*HID)          // 294912  (Wk, Wv)

// ---------------- device scratch ----------------
__device__ float  g_part[4*128];
__device__ float  g_sums[4];
__device__ __half g_x[MROWS*HID];       // hidden_states in fp16
__device__ __half g_qkv[MROWS*NQKV];    // QKV projection (scaled); RoPE applied in place
__device__ __half g_ao[MROWS*HID];      // attention output [B,S,H]

// ---------------- helpers ----------------
__device__ __forceinline__ unsigned sptr(const void* p) {
    return (unsigned)__cvta_generic_to_shared(p);
}
__device__ __forceinline__ unsigned packh2(float x, float y) {
    __half2 h = __floats2half2_rn(x, y);
    return *(unsigned*)&h;
}
__device__ __forceinline__ void ldsm_x4(unsigned& r0, unsigned& r1, unsigned& r2, unsigned& r3,
                                        unsigned addr) {
    asm volatile("ldmatrix.sync.aligned.m8n8.x4.shared.b16 {%0,%1,%2,%3}, [%4];"
                 : "=r"(r0), "=r"(r1), "=r"(r2), "=r"(r3) : "r"(addr));
}
__device__ __forceinline__ void ldsm_x4_t(unsigned& r0, unsigned& r1, unsigned& r2, unsigned& r3,
                                          unsigned addr) {
    asm volatile("ldmatrix.sync.aligned.m8n8.x4.trans.shared.b16 {%0,%1,%2,%3}, [%4];"
                 : "=r"(r0), "=r"(r1), "=r"(r2), "=r"(r3) : "r"(addr));
}
__device__ __forceinline__ void mma_f16(float c[4],
                                        unsigned a0, unsigned a1, unsigned a2, unsigned a3,
                                        unsigned b0, unsigned b1) {
    asm volatile(
        "mma.sync.aligned.m16n8k16.row.col.f32.f16.f16.f32 "
        "{%0,%1,%2,%3}, {%4,%5,%6,%7}, {%8,%9}, {%0,%1,%2,%3};\n"
        : "+f"(c[0]), "+f"(c[1]), "+f"(c[2]), "+f"(c[3])
        : "r"(a0), "r"(a1), "r"(a2), "r"(a3), "r"(b0), "r"(b1));
}

// ---------------- weight |.| reduction (4 matrices fused, deterministic) ----------------
__global__ __launch_bounds__(256) void absum4_kernel(const float* __restrict__ w0,
                                                     const float* __restrict__ w1,
                                                     const float* __restrict__ w2,
                                                     const float* __restrict__ w3) {
    const float* w = (blockIdx.y == 0) ? w0 : (blockIdx.y == 1) ? w1 :
                     (blockIdx.y == 2) ? w2 : w3;
    int n4 = ((blockIdx.y == 0 || blockIdx.y == 3) ? NQEL : NKEL) >> 2;
    __shared__ float red[256];
    float s = 0.f;
    for (int i = blockIdx.x*256 + threadIdx.x; i < n4; i += 128*256) {
        float4 v = *(const float4*)(w + i*4);
        s += fabsf(v.x) + fabsf(v.y) + fabsf(v.z) + fabsf(v.w);
    }
    red[threadIdx.x] = s;
    __syncthreads();
    #pragma unroll
    for (int k = 128; k > 0; k >>= 1) {
        if (threadIdx.x < k) red[threadIdx.x] += red[threadIdx.x + k];
        __syncthreads();
    }
    if (threadIdx.x == 0) g_part[blockIdx.y*128 + blockIdx.x] = red[0];
}

__global__ __launch_bounds__(128) void finalize_kernel() {
    __shared__ float red[128];
    red[threadIdx.x] = g_part[blockIdx.x*128 + threadIdx.x];
    __syncthreads();
    #pragma unroll
    for (int k = 64; k > 0; k >>= 1) {
        if (threadIdx.x < k) red[threadIdx.x] += red[threadIdx.x + k];
        __syncthreads();
    }
    if (threadIdx.x == 0) g_sums[blockIdx.x] = red[0];
}

// ---------------- hidden_states -> fp16 ----------------
__global__ __launch_bounds__(256) void x2h_kernel(const float* __restrict__ x) {
    int i = blockIdx.x*256 + threadIdx.x;          // over MROWS*HID/2
    float2 v = *(const float2*)(x + (size_t)i*2);
    *(__half2*)&g_x[(size_t)i*2] = __floats2half2_rn(v.x, v.y);
}

// ---------------- fp16 tensor-core GEMM with fused ternary quantization ----------------
// C[M,N] = Ah[M,K] * ternary(W)[N,K]^T * scale.  W region selected by block column.
// Block tile 128x128, k-tile 64, 8 warps (2m x 4n), warp tile 64x32, mma m16n8k16.
#define GS 72
template <typename OutT>
__global__ __launch_bounds__(256) void gemm_h(const __half* __restrict__ Ah,
                                              const float* __restrict__ W0,
                                              const float* __restrict__ W1,
                                              const float* __restrict__ W2,
                                              OutT* __restrict__ C,
                                              int M, int N, int K,
                                              int nb1, int nb2,
                                              int si0, int si1, int si2,
                                              float inv0, float inv1, float inv2) {
    __shared__ __half As[128*GS];
    __shared__ __half Bs[128*GS];
    int tid = threadIdx.x;
    int wid = tid >> 5, lane = tid & 31;
    int wm = wid & 1, wn = wid >> 1;
    int g = lane >> 2, tg = lane & 3;
    int bm = blockIdx.y * 128, bn = blockIdx.x * 128;

    const float* W; int ln; float thr, scale;
    if (bn < nb1)      { W = W0; ln = bn;       thr = 0.7f*g_sums[si0]*inv0; scale = g_sums[si0]*inv0; }
    else if (bn < nb2) { W = W1; ln = bn - nb1; thr = 0.7f*g_sums[si1]*inv1; scale = g_sums[si1]*inv1; }
    else               { W = W2; ln = bn - nb2; thr = 0.7f*g_sums[si2]*inv2; scale = g_sums[si2]*inv2; }

    float acc[4][4][4];
    #pragma unroll
    for (int mt = 0; mt < 4; mt++)
        #pragma unroll
        for (int nt = 0; nt < 4; nt++)
            #pragma unroll
            for (int r = 0; r < 4; r++) acc[mt][nt][r] = 0.f;

    for (int k0 = 0; k0 < K; k0 += 64) {
        // load A tile [128][64] fp16
        #pragma unroll
        for (int i = 0; i < 4; i++) {
            int f = tid + i*256;
            int row = f >> 3, c = (f & 7)*8;
            *(uint4*)&As[row*GS + c] = *(const uint4*)(Ah + (size_t)(bm+row)*K + k0 + c);
        }
        // load + quantize W tile [128][64]
        #pragma unroll
        for (int i = 0; i < 8; i++) {
            int f = tid + i*256;
            int row = f >> 4, c = (f & 15)*4;
            float4 v = *(const float4*)(W + (size_t)(ln+row)*K + k0 + c);
            __half q[4];
            q[0] = __float2half((fabsf(v.x) >= thr) ? (v.x > 0.f ? 1.f : -1.f) : 0.f);
            q[1] = __float2half((fabsf(v.y) >= thr) ? (v.y > 0.f ? 1.f : -1.f) : 0.f);
            q[2] = __float2half((fabsf(v.z) >= thr) ? (v.z > 0.f ? 1.f : -1.f) : 0.f);
            q[3] = __float2half((fabsf(v.w) >= thr) ? (v.w > 0.f ? 1.f : -1.f) : 0.f);
            *(uint2*)&Bs[row*GS + c] = *(uint2*)q;
        }
        __syncthreads();

        #pragma unroll
        for (int kt = 0; kt < 4; kt++) {
            unsigned af[4][4];
            #pragma unroll
            for (int mt = 0; mt < 4; mt++) {
                unsigned a = sptr(&As[(wm*64 + mt*16 + (lane & 15))*GS + kt*16 + (lane >> 4)*8]);
                ldsm_x4(af[mt][0], af[mt][1], af[mt][2], af[mt][3], a);
            }
            #pragma unroll
            for (int ntp = 0; ntp < 2; ntp++) {
                unsigned b0e, b0o, b1e, b1o;
                unsigned a = sptr(&Bs[(wn*32 + ntp*16 + (lane & 15))*GS + kt*16 + (lane >> 4)*8]);
                ldsm_x4(b0e, b0o, b1e, b1o, a);
                #pragma unroll
                for (int mt = 0; mt < 4; mt++) {
                    mma_f16(acc[mt][2*ntp  ], af[mt][0], af[mt][1], af[mt][2], af[mt][3], b0e, b1e);
                    mma_f16(acc[mt][2*ntp+1], af[mt][0], af[mt][1], af[mt][2], af[mt][3], b0o, b1o);
                }
            }
        }
        __syncthreads();
    }

    #pragma unroll
    for (int mt = 0; mt < 4; mt++) {
        int row = bm + wm*64 + mt*16 + g;
        #pragma unroll
        for (int nt = 0; nt < 4; nt++) {
            int col = bn + wn*32 + nt*8 + 2*tg;
            if (sizeof(OutT) == 2) {
                __half2* p0 = (__half2*)((__half*)C + (size_t)row*N + col);
                *p0 = __floats2half2_rn(acc[mt][nt][0]*scale, acc[mt][nt][1]*scale);
                __half2* p1 = (__half2*)((__half*)C + (size_t)(row+8)*N + col);
                *p1 = __floats2half2_rn(acc[mt][nt][2]*scale, acc[mt][nt][3]*scale);
            } else {
                float2 v0; v0.x = acc[mt][nt][0]*scale; v0.y = acc[mt][nt][1]*scale;
                *(float2*)((float*)C + (size_t)row*N + col) = v0;
                float2 v1; v1.x = acc[mt][nt][2]*scale; v1.y = acc[mt][nt][3]*scale;
                *(float2*)((float*)C + (size_t)(row+8)*N + col) = v1;
            }
        }
    }
}

// ---------------- in-place RoPE on Q,K columns of g_qkv ----------------
__global__ __launch_bounds__(256) void rope_kernel() {
    int t = blockIdx.x*256 + threadIdx.x;      // over MROWS * 18 * 32
    int m = t / 576;
    int r = t - m*576;
    int u = r >> 5;                            // head unit 0..17 (12 Q + 6 K)
    int c = r & 31;
    int s = m & (SS-1);
    size_t base = (size_t)m*NQKV + u*64 + c;
    float x1 = __half2float(g_qkv[base]);
    float x2 = __half2float(g_qkv[base + 32]);
    float invf = (float)exp(-9.210340371976184 * ((double)c / 32.0));
    float ang = (float)s * invf;
    float co = cosf(ang), sn = sinf(ang);
    g_qkv[base]      = __float2half(x1*co - x2*sn);
    g_qkv[base + 32] = __float2half(x2*co + x1*sn);
}

// ---------------- flash attention, fp16 mma, P kept in registers ----------------
// 8 warps; Q tile 128 (warp w: rows w*16..+15); KV tile 64; reads g_qkv directly.
__global__ __launch_bounds__(256) void attn_kernel() {
    __shared__ __half Qs[128*GS];
    __shared__ __half Ks[64*GS];
    __shared__ __half Vs[64*GS];

    int b = blockIdx.z, h = blockIdx.y;
    int s0 = blockIdx.x * 128;
    int hk = h >> 1;
    int tid = threadIdx.x;
    int wid = tid >> 5, lane = tid & 31;
    int g = lane >> 2, tg = lane & 3;
    int wr = wid * 16;
    int lr = lane & 15, lc = (lane >> 4) * 8;

    const __half* qb = g_qkv + (size_t)(b*SS + s0)*NQKV + h*64;
    const __half* kb = g_qkv + (size_t)(b*SS)*NQKV + HID + hk*64;
    const __half* vb = g_qkv + (size_t)(b*SS)*NQKV + HID + NKV*HD + hk*64;

    // stage Q tile [128][64]
    #pragma unroll
    for (int i = 0; i < 4; i++) {
        int f = tid + i*256;
        int row = f >> 3, c = (f & 7)*8;
        *(uint4*)&Qs[row*GS + c] = *(const uint4*)(qb + (size_t)row*NQKV + c);
    }
    __syncthreads();
    unsigned qf[4][4];
    #pragma unroll
    for (int kt = 0; kt < 4; kt++) {
        unsigned a = sptr(&Qs[(wr + lr)*GS + kt*16 + lc]);
        ldsm_x4(qf[kt][0], qf[kt][1], qf[kt][2], qf[kt][3], a);
    }

    float o[8][4];
    #pragma unroll
    for (int nt = 0; nt < 8; nt++)
        #pragma unroll
        for (int r = 0; r < 4; r++) o[nt][r] = 0.f;
    float m0 = -1e30f, m1 = -1e30f, l0 = 0.f, l1 = 0.f;

    for (int t0 = 0; t0 < SS; t0 += 64) {
        __syncthreads();
        #pragma unroll
        for (int i = 0; i < 2; i++) {
            int f = tid + i*256;
            int row = f >> 3, c = (f & 7)*8;
            *(uint4*)&Ks[row*GS + c] = *(const uint4*)(kb + (size_t)(t0+row)*NQKV + c);
            *(uint4*)&Vs[row*GS + c] = *(const uint4*)(vb + (size_t)(t0+row)*NQKV + c);
        }
        __syncthreads();

        // S = Q K^T  (warp: 16 x 64)
        float sacc[8][4];
        #pragma unroll
        for (int nt = 0; nt < 8; nt++)
            #pragma unroll
            for (int r = 0; r < 4; r++) sacc[nt][r] = 0.f;
        #pragma unroll
        for (int kt = 0; kt < 4; kt++) {
            #pragma unroll
            for (int ntp = 0; ntp < 4; ntp++) {
                unsigned b0e, b0o, b1e, b1o;
                unsigned a = sptr(&Ks[(ntp*16 + lr)*GS + kt*16 + lc]);
                ldsm_x4(b0e, b0o, b1e, b1o, a);
                mma_f16(sacc[2*ntp  ], qf[kt][0], qf[kt][1], qf[kt][2], qf[kt][3], b0e, b1e);
                mma_f16(sacc[2*ntp+1], qf[kt][0], qf[kt][1], qf[kt][2], qf[kt][3], b0o, b1o);
            }
        }

        // online softmax; thread rows r0=wr+g (c0,c1), r1=wr+8+g (c2,c3)
        float mx0 = -1e30f, mx1 = -1e30f;
        #pragma unroll
        for (int nt = 0; nt < 8; nt++) {
            sacc[nt][0] *= 0.125f; sacc[nt][1] *= 0.125f;
            sacc[nt][2] *= 0.125f; sacc[nt][3] *= 0.125f;
            mx0 = fmaxf(mx0, fmaxf(sacc[nt][0], sacc[nt][1]));
            mx1 = fmaxf(mx1, fmaxf(sacc[nt][2], sacc[nt][3]));
        }
        mx0 = fmaxf(mx0, __shfl_xor_sync(0xffffffffu, mx0, 1));
        mx0 = fmaxf(mx0, __shfl_xor_sync(0xffffffffu, mx0, 2));
        mx1 = fmaxf(mx1, __shfl_xor_sync(0xffffffffu, mx1, 1));
        mx1 = fmaxf(mx1, __shfl_xor_sync(0xffffffffu, mx1, 2));
        float mn0 = fmaxf(m0, mx0), mn1 = fmaxf(m1, mx1);
        float al0 = __expf(m0 - mn0), al1 = __expf(m1 - mn1);
        float ls0 = 0.f, ls1 = 0.f;
        unsigned pp[8][2];
        #pragma unroll
        for (int nt = 0; nt < 8; nt++) {
            float p0 = __expf(sacc[nt][0] - mn0);
            float p1 = __expf(sacc[nt][1] - mn0);
            float p2 = __expf(sacc[nt][2] - mn1);
            float p3 = __expf(sacc[nt][3] - mn1);
            ls0 += p0 + p1; ls1 += p2 + p3;
            pp[nt][0] = packh2(p0, p1);
            pp[nt][1] = packh2(p2, p3);
        }
        ls0 += __shfl_xor_sync(0xffffffffu, ls0, 1);
        ls0 += __shfl_xor_sync(0xffffffffu, ls0, 2);
        ls1 += __shfl_xor_sync(0xffffffffu, ls1, 1);
        ls1 += __shfl_xor_sync(0xffffffffu, ls1, 2);
        l0 = l0*al0 + ls0; l1 = l1*al1 + ls1;
        m0 = mn0; m1 = mn1;
        #pragma unroll
        for (int nt = 0; nt < 8; nt++) {
            o[nt][0] *= al0; o[nt][1] *= al0;
            o[nt][2] *= al1; o[nt][3] *= al1;
        }

        // O += P @ V.  A-fragments are the packed C-fragments (layout identity).
        #pragma unroll
        for (int kt = 0; kt < 4; kt++) {
            unsigned a0 = pp[2*kt][0], a1 = pp[2*kt][1];
            unsigned a2 = pp[2*kt+1][0], a3 = pp[2*kt+1][1];
            #pragma unroll
            for (int ntp = 0; ntp < 4; ntp++) {
                unsigned b0e, b1e, b0o, b1o;
                unsigned a = sptr(&Vs[(kt*16 + lr)*GS + ntp*16 + lc]);
                ldsm_x4_t(b0e, b1e, b0o, b1o, a);
                mma_f16(o[2*ntp  ], a0, a1, a2, a3, b0e, b1e);
                mma_f16(o[2*ntp+1], a0, a1, a2, a3, b0o, b1o);
            }
        }
    }

    // epilogue: divide by l, write fp16 [B,S,H]
    float inv0 = 1.f / l0, inv1 = 1.f / l1;
    __half* op = g_ao + (size_t)(b*SS + s0 + wr)*HID + h*64;
    #pragma unroll
    for (int nt = 0; nt < 8; nt++) {
        int col = nt*8 + 2*tg;
        *(__half2*)(op + (size_t)g*HID + col)     = __floats2half2_rn(o[nt][0]*inv0, o[nt][1]*inv0);
        *(__half2*)(op + (size_t)(8+g)*HID + col) = __floats2half2_rn(o[nt][2]*inv1, o[nt][3]*inv1);
    }
}

// ---------------- launch ----------------
extern "C" void kernel_launch(void* const* d_in, const int* in_sizes, int n_in,
                              void* d_out, int out_size) {
    const float* hs = (const float*)d_in[0];
    const float* Wq = (const float*)d_in[1];
    const float* Wk = (const float*)d_in[2];
    const float* Wv = (const float*)d_in[3];
    const float* Wo = (const float*)d_in[4];
    float* out = (float*)d_out;

    __half *p_x, *p_qkv, *p_ao;
    cudaGetSymbolAddress((void**)&p_x,   g_x);
    cudaGetSymbolAddress((void**)&p_qkv, g_qkv);
    cudaGetSymbolAddress((void**)&p_ao,  g_ao);

    // 1) weight scales
    absum4_kernel<<<dim3(128, 4), 256>>>(Wq, Wk, Wv, Wo);
    finalize_kernel<<<4, 128>>>();

    // 2) hidden_states -> fp16
    x2h_kernel<<<(MROWS*HID/2)/256, 256>>>(hs);

    // 3) QKV projection (quantize fused, scaled output, fp16 out)
    gemm_h<__half><<<dim3(NQKV/128, MROWS/128), 256>>>(
        p_x, Wq, Wk, Wv, p_qkv, MROWS, NQKV, HID,
        HID, HID + NKV*HD, 0, 1, 2,
        1.f/(float)NQEL, 1.f/(float)NKEL, 1.f/(float)NKEL);

    // 4) in-place RoPE on Q,K
    rope_kernel<<<(MROWS*576)/256, 256>>>();

    // 5) flash attention
    attn_kernel<<<dim3(SS/128, NH, BB), 256>>>();

    // 6) output projection (quantize fused, fp32 out)
    gemm_h<float><<<dim3(HID/128, MROWS/128), 256>>>(
        p_ao, Wo, Wo, Wo, out, MROWS, HID, HID,
        HID, HID, 3, 3, 3,
        1.f/(float)NQEL, 1.f/(float)NQEL, 1.f/(float)NQEL);
}

// round 5
// speedup vs baseline: 4.9756x; 1.0726x over previous
#include <cuda_runtime.h>
#include <cuda_fp16.h>
#include <math.h>

// ---------------- problem constants ----------------
#define BB   2
#define SS   2048
#define HID  768
#define NH   12
#define NKV  6
#define HD   64
#define MROWS (BB*SS)               // 4096
#define NQKV  (HID + 2*NKV*HD)      // 1536
#define NQEL  (HID*HID)             // 589824  (Wq, Wo)
#define NKEL  (NKV*HD*HID)          // 294912  (Wk, Wv)

// ---------------- device scratch ----------------
__device__ float  g_part[4*128];
__device__ float  g_sums[4];
__device__ __half g_x[MROWS*HID];        // hidden_states in fp16
__device__ __half g_wqkv[NQKV*HID];      // ternary fp16: [Wq;Wk;Wv]
__device__ __half g_who[HID*HID];        // ternary fp16 Wo
__device__ __half g_qkv[MROWS*NQKV];     // QKV projection (scaled); RoPE in place
__device__ __half g_ao[MROWS*HID];       // attention output [B,S,H]

// ---------------- helpers ----------------
__device__ __forceinline__ unsigned sptr(const void* p) {
    return (unsigned)__cvta_generic_to_shared(p);
}
__device__ __forceinline__ unsigned packh2(float x, float y) {
    __half2 h = __floats2half2_rn(x, y);
    return *(unsigned*)&h;
}
__device__ __forceinline__ void cpa16(void* dst, const void* src) {
    asm volatile("cp.async.cg.shared.global [%0], [%1], 16;\n"
                 :: "r"(sptr(dst)), "l"(src));
}
__device__ __forceinline__ void cpa_commit() {
    asm volatile("cp.async.commit_group;\n");
}
template <int N> __device__ __forceinline__ void cpa_wait() {
    asm volatile("cp.async.wait_group %0;\n" :: "n"(N));
}
__device__ __forceinline__ void ldsm_x4(unsigned& r0, unsigned& r1, unsigned& r2, unsigned& r3,
                                        unsigned addr) {
    asm volatile("ldmatrix.sync.aligned.m8n8.x4.shared.b16 {%0,%1,%2,%3}, [%4];"
                 : "=r"(r0), "=r"(r1), "=r"(r2), "=r"(r3) : "r"(addr));
}
__device__ __forceinline__ void ldsm_x4_t(unsigned& r0, unsigned& r1, unsigned& r2, unsigned& r3,
                                          unsigned addr) {
    asm volatile("ldmatrix.sync.aligned.m8n8.x4.trans.shared.b16 {%0,%1,%2,%3}, [%4];"
                 : "=r"(r0), "=r"(r1), "=r"(r2), "=r"(r3) : "r"(addr));
}
__device__ __forceinline__ void mma_f16(float c[4],
                                        unsigned a0, unsigned a1, unsigned a2, unsigned a3,
                                        unsigned b0, unsigned b1) {
    asm volatile(
        "mma.sync.aligned.m16n8k16.row.col.f32.f16.f16.f32 "
        "{%0,%1,%2,%3}, {%4,%5,%6,%7}, {%8,%9}, {%0,%1,%2,%3};\n"
        : "+f"(c[0]), "+f"(c[1]), "+f"(c[2]), "+f"(c[3])
        : "r"(a0), "r"(a1), "r"(a2), "r"(a3), "r"(b0), "r"(b1));
}

// ---------------- weight |.| reduction ----------------
__global__ __launch_bounds__(256) void absum4_kernel(const float* __restrict__ w0,
                                                     const float* __restrict__ w1,
                                                     const float* __restrict__ w2,
                                                     const float* __restrict__ w3) {
    const float* w = (blockIdx.y == 0) ? w0 : (blockIdx.y == 1) ? w1 :
                     (blockIdx.y == 2) ? w2 : w3;
    int n4 = ((blockIdx.y == 0 || blockIdx.y == 3) ? NQEL : NKEL) >> 2;
    __shared__ float red[256];
    float s = 0.f;
    for (int i = blockIdx.x*256 + threadIdx.x; i < n4; i += 128*256) {
        float4 v = *(const float4*)(w + i*4);
        s += fabsf(v.x) + fabsf(v.y) + fabsf(v.z) + fabsf(v.w);
    }
    red[threadIdx.x] = s;
    __syncthreads();
    #pragma unroll
    for (int k = 128; k > 0; k >>= 1) {
        if (threadIdx.x < k) red[threadIdx.x] += red[threadIdx.x + k];
        __syncthreads();
    }
    if (threadIdx.x == 0) g_part[blockIdx.y*128 + blockIdx.x] = red[0];
}

__global__ __launch_bounds__(128) void finalize_kernel() {
    __shared__ float red[128];
    red[threadIdx.x] = g_part[blockIdx.x*128 + threadIdx.x];
    __syncthreads();
    #pragma unroll
    for (int k = 64; k > 0; k >>= 1) {
        if (threadIdx.x < k) red[threadIdx.x] += red[threadIdx.x + k];
        __syncthreads();
    }
    if (threadIdx.x == 0) g_sums[blockIdx.x] = red[0];
}

// ---------------- ternary quantize weights -> fp16 (once) ----------------
__global__ __launch_bounds__(256) void quantw_kernel(const float* __restrict__ w0,
                                                     const float* __restrict__ w1,
                                                     const float* __restrict__ w2,
                                                     const float* __restrict__ w3) {
    int y = blockIdx.y;
    const float* w; __half* dst; int n4; float thr;
    if (y == 0)      { w = w0; dst = g_wqkv;                  n4 = NQEL>>2; thr = 0.7f*g_sums[0]/(float)NQEL; }
    else if (y == 1) { w = w1; dst = g_wqkv + NQEL;           n4 = NKEL>>2; thr = 0.7f*g_sums[1]/(float)NKEL; }
    else if (y == 2) { w = w2; dst = g_wqkv + NQEL + NKEL;    n4 = NKEL>>2; thr = 0.7f*g_sums[2]/(float)NKEL; }
    else             { w = w3; dst = g_who;                   n4 = NQEL>>2; thr = 0.7f*g_sums[3]/(float)NQEL; }
    int i = blockIdx.x*256 + threadIdx.x;
    if (i >= n4) return;
    float4 v = *(const float4*)(w + (size_t)i*4);
    __half q[4];
    q[0] = __float2half((fabsf(v.x) >= thr) ? (v.x > 0.f ? 1.f : -1.f) : 0.f);
    q[1] = __float2half((fabsf(v.y) >= thr) ? (v.y > 0.f ? 1.f : -1.f) : 0.f);
    q[2] = __float2half((fabsf(v.z) >= thr) ? (v.z > 0.f ? 1.f : -1.f) : 0.f);
    q[3] = __float2half((fabsf(v.w) >= thr) ? (v.w > 0.f ? 1.f : -1.f) : 0.f);
    *(uint2*)(dst + (size_t)i*4) = *(uint2*)q;
}

// ---------------- hidden_states -> fp16 ----------------
__global__ __launch_bounds__(256) void x2h_kernel(const float* __restrict__ x) {
    int i = blockIdx.x*256 + threadIdx.x;
    float2 v = *(const float2*)(x + (size_t)i*2);
    *(__half2*)&g_x[(size_t)i*2] = __floats2half2_rn(v.x, v.y);
}

// ---------------- fp16 GEMM, cp.async double-buffered ----------------
// C[M,N] = Ah[M,K] * Wh[N,K]^T * scale(region of bn)
#define GS 72
#define GEMM_SMEM (4*128*GS*2)     // 2 bufs x (A,B) x 128x72 halves
template <typename OutT>
__global__ __launch_bounds__(256) void gemm_h(const __half* __restrict__ Ah,
                                              const __half* __restrict__ Wh,
                                              OutT* __restrict__ C,
                                              int M, int N, int K,
                                              int nb1, int nb2,
                                              int si0, int si1, int si2,
                                              float inv0, float inv1, float inv2) {
    extern __shared__ __half sm[];
    __half* Abuf = sm;                 // [2][128*GS]
    __half* Bbuf = sm + 2*128*GS;      // [2][128*GS]
    int tid = threadIdx.x;
    int wid = tid >> 5, lane = tid & 31;
    int wm = wid & 1, wn = wid >> 1;
    int g = lane >> 2, tg = lane & 3;
    int bm = blockIdx.y * 128, bn = blockIdx.x * 128;

    int lrow = tid >> 3, lcol = (tid & 7)*8;    // cp.async chunk coords (stride 32 rows)

    float acc[4][4][4];
    #pragma unroll
    for (int mt = 0; mt < 4; mt++)
        #pragma unroll
        for (int nt = 0; nt < 4; nt++)
            #pragma unroll
            for (int r = 0; r < 4; r++) acc[mt][nt][r] = 0.f;

    int ntiles = K >> 6;
    // prologue: tile 0 -> buf 0
    #pragma unroll
    for (int i = 0; i < 4; i++) {
        int row = lrow + i*32;
        cpa16(&Abuf[row*GS + lcol], Ah + (size_t)(bm+row)*K + lcol);
        cpa16(&Bbuf[row*GS + lcol], Wh + (size_t)(bn+row)*K + lcol);
    }
    cpa_commit();

    for (int t = 0; t < ntiles; t++) {
        cpa_wait<0>();
        __syncthreads();
        int cur = t & 1, nxt = cur ^ 1;
        if (t + 1 < ntiles) {
            int k0 = (t+1) << 6;
            #pragma unroll
            for (int i = 0; i < 4; i++) {
                int row = lrow + i*32;
                cpa16(&Abuf[nxt*128*GS + row*GS + lcol], Ah + (size_t)(bm+row)*K + k0 + lcol);
                cpa16(&Bbuf[nxt*128*GS + row*GS + lcol], Wh + (size_t)(bn+row)*K + k0 + lcol);
            }
            cpa_commit();
        }
        __half* As = Abuf + cur*128*GS;
        __half* Bs = Bbuf + cur*128*GS;
        #pragma unroll
        for (int kt = 0; kt < 4; kt++) {
            unsigned af[4][4];
            #pragma unroll
            for (int mt = 0; mt < 4; mt++) {
                unsigned a = sptr(&As[(wm*64 + mt*16 + (lane & 15))*GS + kt*16 + (lane >> 4)*8]);
                ldsm_x4(af[mt][0], af[mt][1], af[mt][2], af[mt][3], a);
            }
            #pragma unroll
            for (int ntp = 0; ntp < 2; ntp++) {
                unsigned b0e, b0o, b1e, b1o;
                unsigned a = sptr(&Bs[(wn*32 + ntp*16 + (lane & 15))*GS + kt*16 + (lane >> 4)*8]);
                ldsm_x4(b0e, b0o, b1e, b1o, a);
                #pragma unroll
                for (int mt = 0; mt < 4; mt++) {
                    mma_f16(acc[mt][2*ntp  ], af[mt][0], af[mt][1], af[mt][2], af[mt][3], b0e, b1e);
                    mma_f16(acc[mt][2*ntp+1], af[mt][0], af[mt][1], af[mt][2], af[mt][3], b0o, b1o);
                }
            }
        }
        __syncthreads();
    }

    float scale;
    if (bn < nb1)      scale = g_sums[si0]*inv0;
    else if (bn < nb2) scale = g_sums[si1]*inv1;
    else               scale = g_sums[si2]*inv2;
    #pragma unroll
    for (int mt = 0; mt < 4; mt++) {
        int row = bm + wm*64 + mt*16 + g;
        #pragma unroll
        for (int nt = 0; nt < 4; nt++) {
            int col = bn + wn*32 + nt*8 + 2*tg;
            if (sizeof(OutT) == 2) {
                *(__half2*)((__half*)C + (size_t)row*N + col) =
                    __floats2half2_rn(acc[mt][nt][0]*scale, acc[mt][nt][1]*scale);
                *(__half2*)((__half*)C + (size_t)(row+8)*N + col) =
                    __floats2half2_rn(acc[mt][nt][2]*scale, acc[mt][nt][3]*scale);
            } else {
                float2 v0; v0.x = acc[mt][nt][0]*scale; v0.y = acc[mt][nt][1]*scale;
                *(float2*)((float*)C + (size_t)row*N + col) = v0;
                float2 v1; v1.x = acc[mt][nt][2]*scale; v1.y = acc[mt][nt][3]*scale;
                *(float2*)((float*)C + (size_t)(row+8)*N + col) = v1;
            }
        }
    }
}

// ---------------- in-place RoPE on Q,K ----------------
__global__ __launch_bounds__(256) void rope_kernel() {
    int t = blockIdx.x*256 + threadIdx.x;      // MROWS * 18 * 32
    int m = t / 576;
    int r = t - m*576;
    int u = r >> 5;
    int c = r & 31;
    int s = m & (SS-1);
    size_t base = (size_t)m*NQKV + u*64 + c;
    float x1 = __half2float(g_qkv[base]);
    float x2 = __half2float(g_qkv[base + 32]);
    float invf = (float)exp(-9.210340371976184 * ((double)c / 32.0));
    float ang = (float)s * invf;
    float co = cosf(ang), sn = sinf(ang);
    g_qkv[base]      = __float2half(x1*co - x2*sn);
    g_qkv[base + 32] = __float2half(x2*co + x1*sn);
}

// ---------------- flash attention, cp.async double-buffered KV ----------------
#define ATT_SMEM ((128*GS + 4*64*GS)*2)
__global__ __launch_bounds__(256) void attn_kernel() {
    extern __shared__ __half sm[];
    __half* Qs   = sm;                         // [128][GS]
    __half* Kbuf = sm + 128*GS;                // [2][64*GS]
    __half* Vbuf = sm + 128*GS + 2*64*GS;      // [2][64*GS]

    int b = blockIdx.z, h = blockIdx.y;
    int s0 = blockIdx.x * 128;
    int hk = h >> 1;
    int tid = threadIdx.x;
    int wid = tid >> 5, lane = tid & 31;
    int g = lane >> 2, tg = lane & 3;
    int wr = wid * 16;
    int lr = lane & 15, lc = (lane >> 4) * 8;
    int krow = tid >> 3, kcol = (tid & 7)*8;   // KV cp.async coords (32-row stride)

    const __half* qb = g_qkv + (size_t)(b*SS + s0)*NQKV + h*64;
    const __half* kb = g_qkv + (size_t)(b*SS)*NQKV + HID + hk*64;
    const __half* vb = g_qkv + (size_t)(b*SS)*NQKV + HID + NKV*HD + hk*64;

    // prologue: KV tile 0 -> buf0
    #pragma unroll
    for (int i = 0; i < 2; i++) {
        int row = krow + i*32;
        cpa16(&Kbuf[row*GS + kcol], kb + (size_t)row*NQKV + kcol);
        cpa16(&Vbuf[row*GS + kcol], vb + (size_t)row*NQKV + kcol);
    }
    cpa_commit();

    // stage Q tile [128][64]
    #pragma unroll
    for (int i = 0; i < 4; i++) {
        int f = tid + i*256;
        int row = f >> 3, c = (f & 7)*8;
        *(uint4*)&Qs[row*GS + c] = *(const uint4*)(qb + (size_t)row*NQKV + c);
    }
    __syncthreads();
    unsigned qf[4][4];
    #pragma unroll
    for (int kt = 0; kt < 4; kt++) {
        unsigned a = sptr(&Qs[(wr + lr)*GS + kt*16 + lc]);
        ldsm_x4(qf[kt][0], qf[kt][1], qf[kt][2], qf[kt][3], a);
    }

    float o[8][4];
    #pragma unroll
    for (int nt = 0; nt < 8; nt++)
        #pragma unroll
        for (int r = 0; r < 4; r++) o[nt][r] = 0.f;
    float m0 = -1e30f, m1 = -1e30f, l0 = 0.f, l1 = 0.f;

    for (int t = 0; t < SS/64; t++) {
        cpa_wait<0>();
        __syncthreads();
        int cur = t & 1, nxt = cur ^ 1;
        if (t + 1 < SS/64) {
            int t0 = (t+1)*64;
            #pragma unroll
            for (int i = 0; i < 2; i++) {
                int row = krow + i*32;
                cpa16(&Kbuf[nxt*64*GS + row*GS + kcol], kb + (size_t)(t0+row)*NQKV + kcol);
                cpa16(&Vbuf[nxt*64*GS + row*GS + kcol], vb + (size_t)(t0+row)*NQKV + kcol);
            }
            cpa_commit();
        }
        __half* Ks = Kbuf + cur*64*GS;
        __half* Vs = Vbuf + cur*64*GS;

        // S = Q K^T  (warp: 16 x 64)
        float sacc[8][4];
        #pragma unroll
        for (int nt = 0; nt < 8; nt++)
            #pragma unroll
            for (int r = 0; r < 4; r++) sacc[nt][r] = 0.f;
        #pragma unroll
        for (int kt = 0; kt < 4; kt++) {
            #pragma unroll
            for (int ntp = 0; ntp < 4; ntp++) {
                unsigned b0e, b0o, b1e, b1o;
                unsigned a = sptr(&Ks[(ntp*16 + lr)*GS + kt*16 + lc]);
                ldsm_x4(b0e, b0o, b1e, b1o, a);
                mma_f16(sacc[2*ntp  ], qf[kt][0], qf[kt][1], qf[kt][2], qf[kt][3], b0e, b1e);
                mma_f16(sacc[2*ntp+1], qf[kt][0], qf[kt][1], qf[kt][2], qf[kt][3], b0o, b1o);
            }
        }

        // online softmax
        float mx0 = -1e30f, mx1 = -1e30f;
        #pragma unroll
        for (int nt = 0; nt < 8; nt++) {
            sacc[nt][0] *= 0.125f; sacc[nt][1] *= 0.125f;
            sacc[nt][2] *= 0.125f; sacc[nt][3] *= 0.125f;
            mx0 = fmaxf(mx0, fmaxf(sacc[nt][0], sacc[nt][1]));
            mx1 = fmaxf(mx1, fmaxf(sacc[nt][2], sacc[nt][3]));
        }
        mx0 = fmaxf(mx0, __shfl_xor_sync(0xffffffffu, mx0, 1));
        mx0 = fmaxf(mx0, __shfl_xor_sync(0xffffffffu, mx0, 2));
        mx1 = fmaxf(mx1, __shfl_xor_sync(0xffffffffu, mx1, 1));
        mx1 = fmaxf(mx1, __shfl_xor_sync(0xffffffffu, mx1, 2));
        float mn0 = fmaxf(m0, mx0), mn1 = fmaxf(m1, mx1);
        float al0 = __expf(m0 - mn0), al1 = __expf(m1 - mn1);
        float ls0 = 0.f, ls1 = 0.f;
        unsigned pp[8][2];
        #pragma unroll
        for (int nt = 0; nt < 8; nt++) {
            float p0 = __expf(sacc[nt][0] - mn0);
            float p1 = __expf(sacc[nt][1] - mn0);
            float p2 = __expf(sacc[nt][2] - mn1);
            float p3 = __expf(sacc[nt][3] - mn1);
            ls0 += p0 + p1; ls1 += p2 + p3;
            pp[nt][0] = packh2(p0, p1);
            pp[nt][1] = packh2(p2, p3);
        }
        ls0 += __shfl_xor_sync(0xffffffffu, ls0, 1);
        ls0 += __shfl_xor_sync(0xffffffffu, ls0, 2);
        ls1 += __shfl_xor_sync(0xffffffffu, ls1, 1);
        ls1 += __shfl_xor_sync(0xffffffffu, ls1, 2);
        l0 = l0*al0 + ls0; l1 = l1*al1 + ls1;
        m0 = mn0; m1 = mn1;
        #pragma unroll
        for (int nt = 0; nt < 8; nt++) {
            o[nt][0] *= al0; o[nt][1] *= al0;
            o[nt][2] *= al1; o[nt][3] *= al1;
        }

        // O += P @ V (P fragments stay in registers)
        #pragma unroll
        for (int kt = 0; kt < 4; kt++) {
            unsigned a0 = pp[2*kt][0], a1 = pp[2*kt][1];
            unsigned a2 = pp[2*kt+1][0], a3 = pp[2*kt+1][1];
            #pragma unroll
            for (int ntp = 0; ntp < 4; ntp++) {
                unsigned b0e, b1e, b0o, b1o;
                unsigned a = sptr(&Vs[(kt*16 + lr)*GS + ntp*16 + lc]);
                ldsm_x4_t(b0e, b1e, b0o, b1o, a);
                mma_f16(o[2*ntp  ], a0, a1, a2, a3, b0e, b1e);
                mma_f16(o[2*ntp+1], a0, a1, a2, a3, b0o, b1o);
            }
        }
        __syncthreads();
    }

    // epilogue
    float inv0 = 1.f / l0, inv1 = 1.f / l1;
    __half* op = g_ao + (size_t)(b*SS + s0 + wr)*HID + h*64;
    #pragma unroll
    for (int nt = 0; nt < 8; nt++) {
        int col = nt*8 + 2*tg;
        *(__half2*)(op + (size_t)g*HID + col)     = __floats2half2_rn(o[nt][0]*inv0, o[nt][1]*inv0);
        *(__half2*)(op + (size_t)(8+g)*HID + col) = __floats2half2_rn(o[nt][2]*inv1, o[nt][3]*inv1);
    }
}

// ---------------- launch ----------------
extern "C" void kernel_launch(void* const* d_in, const int* in_sizes, int n_in,
                              void* d_out, int out_size) {
    const float* hs = (const float*)d_in[0];
    const float* Wq = (const float*)d_in[1];
    const float* Wk = (const float*)d_in[2];
    const float* Wv = (const float*)d_in[3];
    const float* Wo = (const float*)d_in[4];
    float* out = (float*)d_out;

    __half *p_x, *p_wqkv, *p_who, *p_qkv, *p_ao;
    cudaGetSymbolAddress((void**)&p_x,    g_x);
    cudaGetSymbolAddress((void**)&p_wqkv, g_wqkv);
    cudaGetSymbolAddress((void**)&p_who,  g_who);
    cudaGetSymbolAddress((void**)&p_qkv,  g_qkv);
    cudaGetSymbolAddress((void**)&p_ao,   g_ao);

    cudaFuncSetAttribute(gemm_h<__half>, cudaFuncAttributeMaxDynamicSharedMemorySize, GEMM_SMEM);
    cudaFuncSetAttribute(gemm_h<float>,  cudaFuncAttributeMaxDynamicSharedMemorySize, GEMM_SMEM);
    cudaFuncSetAttribute(attn_kernel,    cudaFuncAttributeMaxDynamicSharedMemorySize, ATT_SMEM);

    // 1) weight scales
    absum4_kernel<<<dim3(128, 4), 256>>>(Wq, Wk, Wv, Wo);
    finalize_kernel<<<4, 128>>>();

    // 2) ternary-quantize weights to fp16 (once)
    quantw_kernel<<<dim3((NQEL/4 + 255)/256, 4), 256>>>(Wq, Wk, Wv, Wo);

    // 3) hidden_states -> fp16
    x2h_kernel<<<(MROWS*HID/2)/256, 256>>>(hs);

    // 4) QKV projection
    gemm_h<__half><<<dim3(NQKV/128, MROWS/128), 256, GEMM_SMEM>>>(
        p_x, p_wqkv, p_qkv, MROWS, NQKV, HID,
        HID, HID + NKV*HD, 0, 1, 2,
        1.f/(float)NQEL, 1.f/(float)NKEL, 1.f/(float)NKEL);

    // 5) in-place RoPE on Q,K
    rope_kernel<<<(MROWS*576)/256, 256>>>();

    // 6) flash attention
    attn_kernel<<<dim3(SS/128, NH, BB), 256, ATT_SMEM>>>();

    // 7) output projection
    gemm_h<float><<<dim3(HID/128, MROWS/128), 256, GEMM_SMEM>>>(
        p_ao, p_who, out, MROWS, HID, HID,
        HID, HID, 3, 3, 3,
        1.f/(float)NQEL, 1.f/(float)NQEL, 1.f/(float)NQEL);
}